// round 10
// baseline (speedup 1.0000x reference)
#include <cuda_runtime.h>
#include <cstdint>
#include <math.h>

#define N_B 64
#define T_T 512
#define D_D 512
#define H_H 512

// Scratch (device globals: allocation-free per harness rules)
__device__ float g_xwx[(size_t)N_B * T_T * H_H];   // 67 MB input projections
__device__ float g_hbuf[2 * 8 * 8 * 512];          // double-buffered h exchange
__device__ unsigned int g_flag[128];               // per (group, producer) step flags

__global__ void init_flags_kernel() {
    if (threadIdx.x < 128) g_flag[threadIdx.x] = 0u;
}

// ---- packed fp32x2 helpers (Blackwell FFMA2 path) ----
__device__ __forceinline__ unsigned long long ffma2(
    unsigned long long a, unsigned long long b, unsigned long long c) {
    unsigned long long d;
    asm("fma.rn.f32x2 %0, %1, %2, %3;" : "=l"(d) : "l"(a), "l"(b), "l"(c));
    return d;
}
__device__ __forceinline__ unsigned long long fadd2(
    unsigned long long a, unsigned long long b) {
    unsigned long long d;
    asm("add.rn.f32x2 %0, %1, %2;" : "=l"(d) : "l"(a), "l"(b));
    return d;
}
__device__ __forceinline__ unsigned long long pack2(float lo, float hi) {
    unsigned long long r;
    asm("mov.b64 %0, {%1, %2};" : "=l"(r) : "f"(lo), "f"(hi));
    return r;
}

// ---------------------------------------------------------------------------
// Phase 1: g_xwx[m][h] = x[m][:] @ Wx[:][h] + b[h]  (32768 x 512 SGEMM)
// ---------------------------------------------------------------------------
#define BM 128
#define BN 128
#define BK 16

__global__ __launch_bounds__(256, 2) void xwx_gemm_kernel(
    const float* __restrict__ A,
    const float* __restrict__ B,
    const float* __restrict__ bias)
{
    __shared__ float As[BK][BM + 4];
    __shared__ float Bs[BK][BN + 4];

    const int tid = threadIdx.x;
    const int bm = blockIdx.y * BM;
    const int bn = blockIdx.x * BN;

    const int ty = tid >> 4;
    const int tx = tid & 15;

    const int aRow = tid >> 2;
    const int aCol = (tid & 3) << 2;
    const int bRow = tid >> 5;
    const int bCol = (tid & 31) << 2;

    unsigned long long acc2[8][4];
#pragma unroll
    for (int i = 0; i < 8; i++)
#pragma unroll
        for (int j = 0; j < 4; j++) acc2[i][j] = 0ull;

    for (int kt = 0; kt < D_D; kt += BK) {
#pragma unroll
        for (int rr = 0; rr < BM; rr += 64) {
            float4 a = *(const float4*)&A[(size_t)(bm + aRow + rr) * D_D + kt + aCol];
            As[aCol + 0][aRow + rr] = a.x;
            As[aCol + 1][aRow + rr] = a.y;
            As[aCol + 2][aRow + rr] = a.z;
            As[aCol + 3][aRow + rr] = a.w;
        }
#pragma unroll
        for (int rr = 0; rr < BK; rr += 8) {
            float4 b4 = *(const float4*)&B[(size_t)(kt + bRow + rr) * H_H + bn + bCol];
            *(float4*)&Bs[bRow + rr][bCol] = b4;
        }
        __syncthreads();

#pragma unroll
        for (int k = 0; k < BK; k++) {
            float4 a0 = *(const float4*)&As[k][ty * 4];
            float4 a1 = *(const float4*)&As[k][64 + ty * 4];
            ulonglong2 b01 = *(const ulonglong2*)&Bs[k][tx * 4];
            ulonglong2 b23 = *(const ulonglong2*)&Bs[k][64 + tx * 4];

            unsigned long long av[8];
            av[0] = pack2(a0.x, a0.x); av[1] = pack2(a0.y, a0.y);
            av[2] = pack2(a0.z, a0.z); av[3] = pack2(a0.w, a0.w);
            av[4] = pack2(a1.x, a1.x); av[5] = pack2(a1.y, a1.y);
            av[6] = pack2(a1.z, a1.z); av[7] = pack2(a1.w, a1.w);

#pragma unroll
            for (int i = 0; i < 8; i++) {
                acc2[i][0] = ffma2(av[i], b01.x, acc2[i][0]);
                acc2[i][1] = ffma2(av[i], b01.y, acc2[i][1]);
                acc2[i][2] = ffma2(av[i], b23.x, acc2[i][2]);
                acc2[i][3] = ffma2(av[i], b23.y, acc2[i][3]);
            }
        }
        __syncthreads();
    }

#pragma unroll
    for (int i = 0; i < 8; i++) {
        int row = bm + ((i < 4) ? (ty * 4 + i) : (64 + ty * 4 + (i - 4)));
#pragma unroll
        for (int jj = 0; jj < 2; jj++) {
            int col = bn + jj * 64 + tx * 4;
            ulonglong2 bb = *(const ulonglong2*)&bias[col];
            ulonglong2 v;
            v.x = fadd2(acc2[i][jj * 2 + 0], bb.x);
            v.y = fadd2(acc2[i][jj * 2 + 1], bb.y);
            *(ulonglong2*)&g_xwx[(size_t)row * H_H + col] = v;
        }
    }
}

// ---------------------------------------------------------------------------
// Phase 2: flag-pipelined scan. 8 groups x 16 CTAs; CTA = 8 rows x 32 cols,
// Wh slice SMEM-resident. Exchange via compact L2 hbuf + per-producer
// release/acquire flags. Half-warp spins only on the one flag it consumes.
// ---------------------------------------------------------------------------
#define SWH_F  (512 * 32)      // 32768 floats
#define CH     292             // sHx chunk stride (8*36 + 4 stagger)
#define SHX_F  (16 * CH)
#define RPAD   288             // 8*36 reduction row per kp
#define SRED_F (16 * RPAD)
#define SMEM_SCAN_BYTES ((SWH_F + SHX_F + SRED_F) * 4)

__global__ __launch_bounds__(256, 1) void rnn_scan_kernel(
    const float* __restrict__ h0,   // (64, 512)
    const float* __restrict__ Wh,   // (512, 512)
    float* __restrict__ out)        // (64, 512, 512)
{
    extern __shared__ float smem[];
    float* sWh  = smem;             // [512][32]
    float* sHx  = smem + SWH_F;     // [16 chunks][8 rows][36]
    float* sRed = sHx + SHX_F;      // [16][8][36]

    const int tid = threadIdx.x;
    const int g   = blockIdx.x >> 4;    // batch group 0..7
    const int c   = blockIdx.x & 15;    // column slice (producer id) 0..15
    const int c0  = c << 5;
    const int n0  = g << 3;

    // Load Wh column slice once: sWh[k*32 + j] = Wh[k][c0+j]
    for (int i = tid; i < 4096; i += 256) {
        int k = i >> 3, j4 = (i & 7) << 2;
        *(float4*)&sWh[k * 32 + j4] = *(const float4*)&Wh[(size_t)k * H_H + c0 + j4];
    }

    const int r   = tid & 7;            // batch row for slab
    const int cg  = (tid >> 3) & 1;     // column half (16 cols)
    const int kp  = tid >> 4;           // k-chunk / producer index 0..15
    const int k0  = kp << 5;
    const int or_ = tid >> 5;           // owned output row
    const int oc_ = tid & 31;           // owned output col
    const int ci  = tid & 15;           // index within kp cohort (half-warp)
    const int row = ci >> 1;            // h row this thread stages
    const int half= ci & 1;             // 16-float half of the 32-k slice

    const unsigned int* fa = &g_flag[(g << 4) + kp];

    size_t oidx = (size_t)(n0 + or_) * T_T * H_H + c0 + oc_;
    float xv = __ldcg(&g_xwx[oidx]);    // xwx for t=0

    __syncthreads();

    const float* wb = &sWh[(k0 << 5) + (cg << 4)];
    const float* hrow = &sHx[kp * CH + r * 36];

    for (int t = 0; t < T_T; t++) {
        // ---- wait for this cohort's producer (half-warp-granular) ----
        if (t > 0) {
            unsigned int fv;
            do {
                asm volatile("ld.acquire.gpu.global.u32 %0, [%1];"
                             : "=r"(fv) : "l"(fa) : "memory");
            } while (fv < (unsigned int)t);
        }
        // ---- cohort stages its 8x32 h slice into SMEM ----
        {
            const float* hb = (t == 0)
                ? (h0 + (size_t)n0 * H_H)
                : (g_hbuf + (size_t)((((t - 1) & 1) << 3) + g) * 4096);
            const float4* src = (const float4*)(hb + row * 512 + k0 + (half << 4));
            float4 v0 = __ldcg(src + 0);
            float4 v1 = __ldcg(src + 1);
            float4 v2 = __ldcg(src + 2);
            float4 v3 = __ldcg(src + 3);
            float* hd = &sHx[kp * CH + row * 36 + (half << 4)];
            *(float4*)(hd + 0)  = v0;
            *(float4*)(hd + 4)  = v1;
            *(float4*)(hd + 8)  = v2;
            *(float4*)(hd + 12) = v3;
        }
        __syncwarp();

        // ---- packed FMA slab: 16 cols x 32 k ----
        unsigned long long a0 = 0, a1 = 0, a2 = 0, a3 = 0,
                           a4 = 0, a5 = 0, a6 = 0, a7 = 0;
#pragma unroll
        for (int kb = 0; kb < 8; kb++) {
            float4 h4 = *(const float4*)&hrow[kb << 2];
#pragma unroll
            for (int q = 0; q < 4; q++) {
                float hv = (q == 0) ? h4.x : (q == 1) ? h4.y : (q == 2) ? h4.z : h4.w;
                unsigned long long h2 = pack2(hv, hv);
                const float* wp = wb + (((kb << 2) + q) << 5);
                ulonglong2 wA = *(const ulonglong2*)(wp + 0);
                ulonglong2 wB = *(const ulonglong2*)(wp + 4);
                ulonglong2 wC = *(const ulonglong2*)(wp + 8);
                ulonglong2 wD = *(const ulonglong2*)(wp + 12);
                a0 = ffma2(h2, wA.x, a0);
                a1 = ffma2(h2, wA.y, a1);
                a2 = ffma2(h2, wB.x, a2);
                a3 = ffma2(h2, wB.y, a3);
                a4 = ffma2(h2, wC.x, a4);
                a5 = ffma2(h2, wC.y, a5);
                a6 = ffma2(h2, wD.x, a6);
                a7 = ffma2(h2, wD.y, a7);
            }
        }
        // ---- write k-split partials ----
        {
            float* dst = &sRed[kp * RPAD + r * 36 + (cg << 4)];
            *(ulonglong2*)(dst + 0)  = make_ulonglong2(a0, a1);
            *(ulonglong2*)(dst + 4)  = make_ulonglong2(a2, a3);
            *(ulonglong2*)(dst + 8)  = make_ulonglong2(a4, a5);
            *(ulonglong2*)(dst + 12) = make_ulonglong2(a6, a7);
        }
        __syncthreads();

        // ---- reduce 16 partials (fixed order), activation, store ----
        float v = 0.f;
#pragma unroll
        for (int p = 0; p < 16; p++)
            v += sRed[p * RPAD + or_ * 36 + oc_];
        v = tanhf(v + xv);
        out[oidx] = v;

        if (t < T_T - 1) {
            // publish h slice to compact exchange buffer
            g_hbuf[(size_t)(((t & 1) << 3) + g) * 4096 + or_ * 512 + c0 + oc_] = v;
            // prefetch next xwx (independent, hides L2/DRAM latency)
            oidx += H_H;
            xv = __ldcg(&g_xwx[oidx]);
            __syncthreads();   // all slice stores done + sRed reads done
            if (tid == 0) {
                asm volatile("st.release.gpu.global.u32 [%0], %1;"
                             :: "l"(&g_flag[(g << 4) + c]),
                                "r"((unsigned int)(t + 1)) : "memory");
            }
        }
    }
}

// ---------------------------------------------------------------------------
extern "C" void kernel_launch(void* const* d_in, const int* in_sizes, int n_in,
                              void* d_out, int out_size) {
    (void)in_sizes; (void)n_in; (void)out_size;
    const float* x  = (const float*)d_in[0];
    const float* h0 = (const float*)d_in[1];
    const float* Wx = (const float*)d_in[2];
    const float* Wh = (const float*)d_in[3];
    const float* b  = (const float*)d_in[4];
    float* out = (float*)d_out;

    init_flags_kernel<<<1, 128>>>();

    dim3 g1(H_H / BN, (N_B * T_T) / BM);   // (4, 256)
    xwx_gemm_kernel<<<g1, 256>>>(x, Wx, b);

    cudaFuncSetAttribute((const void*)rnn_scan_kernel,
                         cudaFuncAttributeMaxDynamicSharedMemorySize,
                         SMEM_SCAN_BYTES);
    rnn_scan_kernel<<<128, 256, SMEM_SCAN_BYTES>>>(h0, Wh, out);
}

// round 11
// speedup vs baseline: 2.0916x; 2.0916x over previous
#include <cuda_runtime.h>
#include <cstdint>
#include <math.h>

#define N_B 64
#define T_T 512
#define D_D 512
#define H_H 512

// Scratch (device globals: allocation-free per harness rules)
__device__ float g_xwx[(size_t)N_B * T_T * H_H];   // 67 MB input projections
__device__ float g_hbuf[2 * 8 * 8 * 512];          // double-buffered compact h exchange
__device__ unsigned int g_sync[8];                 // per-group step counters

__global__ void init_sync_kernel() {
    if (threadIdx.x < 8) g_sync[threadIdx.x] = 0u;
}

// ---- packed fp32x2 helpers (Blackwell FFMA2 path) ----
__device__ __forceinline__ unsigned long long ffma2(
    unsigned long long a, unsigned long long b, unsigned long long c) {
    unsigned long long d;
    asm("fma.rn.f32x2 %0, %1, %2, %3;" : "=l"(d) : "l"(a), "l"(b), "l"(c));
    return d;
}
__device__ __forceinline__ unsigned long long fadd2(
    unsigned long long a, unsigned long long b) {
    unsigned long long d;
    asm("add.rn.f32x2 %0, %1, %2;" : "=l"(d) : "l"(a), "l"(b));
    return d;
}
__device__ __forceinline__ unsigned long long pack2(float lo, float hi) {
    unsigned long long r;
    asm("mov.b64 %0, {%1, %2};" : "=l"(r) : "f"(lo), "f"(hi));
    return r;
}

// ---------------------------------------------------------------------------
// Phase 1: g_xwx[m][h] = x[m][:] @ Wx[:][h] + b[h]  (32768 x 512 SGEMM)
// ---------------------------------------------------------------------------
#define BM 128
#define BN 128
#define BK 16

__global__ __launch_bounds__(256, 2) void xwx_gemm_kernel(
    const float* __restrict__ A,
    const float* __restrict__ B,
    const float* __restrict__ bias)
{
    __shared__ float As[BK][BM + 4];
    __shared__ float Bs[BK][BN + 4];

    const int tid = threadIdx.x;
    const int bm = blockIdx.y * BM;
    const int bn = blockIdx.x * BN;

    const int ty = tid >> 4;
    const int tx = tid & 15;

    const int aRow = tid >> 2;
    const int aCol = (tid & 3) << 2;
    const int bRow = tid >> 5;
    const int bCol = (tid & 31) << 2;

    unsigned long long acc2[8][4];
#pragma unroll
    for (int i = 0; i < 8; i++)
#pragma unroll
        for (int j = 0; j < 4; j++) acc2[i][j] = 0ull;

    for (int kt = 0; kt < D_D; kt += BK) {
#pragma unroll
        for (int rr = 0; rr < BM; rr += 64) {
            float4 a = *(const float4*)&A[(size_t)(bm + aRow + rr) * D_D + kt + aCol];
            As[aCol + 0][aRow + rr] = a.x;
            As[aCol + 1][aRow + rr] = a.y;
            As[aCol + 2][aRow + rr] = a.z;
            As[aCol + 3][aRow + rr] = a.w;
        }
#pragma unroll
        for (int rr = 0; rr < BK; rr += 8) {
            float4 b4 = *(const float4*)&B[(size_t)(kt + bRow + rr) * H_H + bn + bCol];
            *(float4*)&Bs[bRow + rr][bCol] = b4;
        }
        __syncthreads();

#pragma unroll
        for (int k = 0; k < BK; k++) {
            float4 a0 = *(const float4*)&As[k][ty * 4];
            float4 a1 = *(const float4*)&As[k][64 + ty * 4];
            ulonglong2 b01 = *(const ulonglong2*)&Bs[k][tx * 4];
            ulonglong2 b23 = *(const ulonglong2*)&Bs[k][64 + tx * 4];

            unsigned long long av[8];
            av[0] = pack2(a0.x, a0.x); av[1] = pack2(a0.y, a0.y);
            av[2] = pack2(a0.z, a0.z); av[3] = pack2(a0.w, a0.w);
            av[4] = pack2(a1.x, a1.x); av[5] = pack2(a1.y, a1.y);
            av[6] = pack2(a1.z, a1.z); av[7] = pack2(a1.w, a1.w);

#pragma unroll
            for (int i = 0; i < 8; i++) {
                acc2[i][0] = ffma2(av[i], b01.x, acc2[i][0]);
                acc2[i][1] = ffma2(av[i], b01.y, acc2[i][1]);
                acc2[i][2] = ffma2(av[i], b23.x, acc2[i][2]);
                acc2[i][3] = ffma2(av[i], b23.y, acc2[i][3]);
            }
        }
        __syncthreads();
    }

#pragma unroll
    for (int i = 0; i < 8; i++) {
        int row = bm + ((i < 4) ? (ty * 4 + i) : (64 + ty * 4 + (i - 4)));
#pragma unroll
        for (int jj = 0; jj < 2; jj++) {
            int col = bn + jj * 64 + tx * 4;
            ulonglong2 bb = *(const ulonglong2*)&bias[col];
            ulonglong2 v;
            v.x = fadd2(acc2[i][jj * 2 + 0], bb.x);
            v.y = fadd2(acc2[i][jj * 2 + 1], bb.y);
            *(ulonglong2*)&g_xwx[(size_t)row * H_H + col] = v;
        }
    }
}

// ---------------------------------------------------------------------------
// Phase 2: persistent scan (R5 topology). 128 CTAs = 8 groups (8 rows) x 16
// column-slice CTAs (32 cols). Wh slice SMEM-resident, BANK-STAGGERED per kp
// chunk (stride 1032 floats -> conflict-free LDS.128 weight reads).
// Exchange: compact double-buffered g_hbuf in L2; barrier: one
// red.release.gpu per CTA + acquire-spin by thread 0.
// ---------------------------------------------------------------------------
#define KPSTRIDE 1032            // 32k * 32cols + 8 stagger floats per kp chunk
#define SWH_F    (16 * KPSTRIDE) // 16512 floats
#define HPAD     516             // padded h row
#define RPAD     288             // 8*36 reduction row per kp
#define SMEM_SCAN_BYTES ((SWH_F + 8 * HPAD + 16 * RPAD) * 4)

__global__ __launch_bounds__(256, 1) void rnn_scan_kernel(
    const float* __restrict__ h0,   // (64, 512)
    const float* __restrict__ Wh,   // (512, 512)
    float* __restrict__ out)        // (64, 512, 512)
{
    extern __shared__ float smem[];
    float* sWh  = smem;                  // [16 kp][32 k][32 cols] stride 1032
    float* sH   = sWh + SWH_F;           // [8][516]
    float* sRed = sH + 8 * HPAD;         // [16][8][36]

    const int tid = threadIdx.x;
    const int g   = blockIdx.x >> 4;     // batch group 0..7
    const int c   = blockIdx.x & 15;     // column slice 0..15
    const int c0  = c << 5;
    const int n0  = g << 3;

    // Load Wh column slice into staggered layout:
    // sWh[(k>>5)*1032 + (k&31)*32 + j] = Wh[k][c0+j]
    for (int i = tid; i < 4096; i += 256) {
        int k = i >> 3, j4 = (i & 7) << 2;
        *(float4*)&sWh[(k >> 5) * KPSTRIDE + (k & 31) * 32 + j4] =
            *(const float4*)&Wh[(size_t)k * H_H + c0 + j4];
    }

    const int r   = tid & 7;             // batch row for slab
    const int cg  = (tid >> 3) & 1;      // column half (16 cols)
    const int kp  = tid >> 4;            // k-split 0..15
    const int or_ = tid >> 5;            // owned output row
    const int oc_ = tid & 31;            // owned output col

    size_t oidx = ((size_t)(n0 + or_) * T_T) * H_H + c0 + oc_;
    float xv = __ldcg(&g_xwx[oidx]);     // xwx for t=0

    const float* wbase = &sWh[kp * KPSTRIDE + (cg << 4)];
    unsigned int* syncp = &g_sync[g];

    __syncthreads();

    for (int t = 0; t < T_T; t++) {
        // ---- load h_{t-1}: contiguous 4096-float block (h0 rows n0..n0+7
        //      are contiguous; hbuf group block is contiguous by design) ----
        {
            const float4* hb = (t == 0)
                ? (const float4*)(h0 + (size_t)n0 * H_H)
                : (const float4*)(g_hbuf + (size_t)((((t - 1) & 1) << 3) + g) * 4096);
#pragma unroll
            for (int i = tid; i < 1024; i += 256) {
                float4 v = __ldcg(hb + i);
                *(float4*)&sH[(i >> 7) * HPAD + ((i & 127) << 2)] = v;
            }
        }
        __syncthreads();

        // ---- packed FMA slab: 16 cols x 32 k (conflict-free weight LDS) ----
        unsigned long long a0 = 0, a1 = 0, a2 = 0, a3 = 0,
                           a4 = 0, a5 = 0, a6 = 0, a7 = 0;
        const float* hrow = &sH[r * HPAD + (kp << 5)];
#pragma unroll 8
        for (int kk = 0; kk < 32; kk++) {
            float hv = hrow[kk];
            unsigned long long h2 = pack2(hv, hv);
            const float* wp = wbase + (kk << 5);
            ulonglong2 wA = *(const ulonglong2*)(wp + 0);
            ulonglong2 wB = *(const ulonglong2*)(wp + 4);
            ulonglong2 wC = *(const ulonglong2*)(wp + 8);
            ulonglong2 wD = *(const ulonglong2*)(wp + 12);
            a0 = ffma2(h2, wA.x, a0);
            a1 = ffma2(h2, wA.y, a1);
            a2 = ffma2(h2, wB.x, a2);
            a3 = ffma2(h2, wB.y, a3);
            a4 = ffma2(h2, wC.x, a4);
            a5 = ffma2(h2, wC.y, a5);
            a6 = ffma2(h2, wD.x, a6);
            a7 = ffma2(h2, wD.y, a7);
        }

        // ---- write k-split partials ----
        {
            float* dst = &sRed[kp * RPAD + r * 36 + (cg << 4)];
            *(ulonglong2*)(dst + 0)  = make_ulonglong2(a0, a1);
            *(ulonglong2*)(dst + 4)  = make_ulonglong2(a2, a3);
            *(ulonglong2*)(dst + 8)  = make_ulonglong2(a4, a5);
            *(ulonglong2*)(dst + 12) = make_ulonglong2(a6, a7);
        }
        __syncthreads();

        // ---- reduce 16 partials (fixed order), activation, store ----
        float v = 0.f;
#pragma unroll
        for (int p = 0; p < 16; p++)
            v += sRed[p * RPAD + or_ * 36 + oc_];
        v = tanhf(v + xv);
        out[oidx] = v;

        if (t < T_T - 1) {
            // publish h_t to compact exchange buffer (parity t&1)
            g_hbuf[(size_t)(((t & 1) << 3) + g) * 4096 + (or_ << 9) + c0 + oc_] = v;
            // prefetch next xwx (independent; hides L2/DRAM latency)
            oidx += H_H;
            xv = __ldcg(&g_xwx[oidx]);
            __syncthreads();   // publishes + sRed reads complete block-wide
            if (tid == 0) {
                // release-atomic: orders the block's publishes, no membar.gpu
                asm volatile("red.release.gpu.global.add.u32 [%0], %1;"
                             :: "l"(syncp), "r"(1u) : "memory");
                const unsigned int target = (unsigned int)(t + 1) << 4;
                unsigned int fv;
                do {
                    asm volatile("ld.acquire.gpu.global.u32 %0, [%1];"
                                 : "=r"(fv) : "l"(syncp) : "memory");
                } while (fv < target);
            }
            __syncthreads();
        }
    }
}

// ---------------------------------------------------------------------------
extern "C" void kernel_launch(void* const* d_in, const int* in_sizes, int n_in,
                              void* d_out, int out_size) {
    (void)in_sizes; (void)n_in; (void)out_size;
    const float* x  = (const float*)d_in[0];
    const float* h0 = (const float*)d_in[1];
    const float* Wx = (const float*)d_in[2];
    const float* Wh = (const float*)d_in[3];
    const float* b  = (const float*)d_in[4];
    float* out = (float*)d_out;

    init_sync_kernel<<<1, 32>>>();

    dim3 g1(H_H / BN, (N_B * T_T) / BM);   // (4, 256)
    xwx_gemm_kernel<<<g1, 256>>>(x, Wx, b);

    cudaFuncSetAttribute((const void*)rnn_scan_kernel,
                         cudaFuncAttributeMaxDynamicSharedMemorySize,
                         SMEM_SCAN_BYTES);
    rnn_scan_kernel<<<128, 256, SMEM_SCAN_BYTES>>>(h0, Wh, out);
}